// round 15
// baseline (speedup 1.0000x reference)
#include <cuda_runtime.h>
#include <cuda_fp16.h>
#include <stdint.h>

#define BATCH 4
#define DIM 256
#define LL 2048
#define HEADS 8
#define DHEAD 64
#define HID 512
#define QKV_ROWS 1536
#define QPRESCALE 0.18033688011112042f
#define NSPLIT 4
#define STILES 8            // KV tiles per split (32 / NSPLIT)

#define NX (BATCH * DIM * LL)
#define NQ (QKV_ROWS * DIM)
#define NO (DIM * HID)

__device__ __half g_qkv [(size_t)BATCH * QKV_ROWS * LL];
__device__ __half g_ao  [(size_t)BATCH * HID * LL];
__device__ __half g_xh  [NX];
__device__ __half g_wqk [NQ];
__device__ __half g_wo  [NO];
__device__ float  g_opf [(size_t)NSPLIT * BATCH * HID * LL];    // O partials
__device__ float  g_lpf [(size_t)NSPLIT * BATCH * HEADS * LL];  // l partials

// ---------------------------------------------------------------------------
// PTX helpers
// ---------------------------------------------------------------------------
__device__ __forceinline__ uint32_t smem_u32(const void* p) {
    return (uint32_t)__cvta_generic_to_shared(p);
}
__device__ __forceinline__ void ldsm_x4(uint32_t r[4], uint32_t a) {
    asm volatile("ldmatrix.sync.aligned.m8n8.x4.shared.b16 {%0,%1,%2,%3}, [%4];"
        : "=r"(r[0]), "=r"(r[1]), "=r"(r[2]), "=r"(r[3]) : "r"(a));
}
__device__ __forceinline__ void ldsm_x4t(uint32_t r[4], uint32_t a) {
    asm volatile("ldmatrix.sync.aligned.m8n8.x4.trans.shared.b16 {%0,%1,%2,%3}, [%4];"
        : "=r"(r[0]), "=r"(r[1]), "=r"(r[2]), "=r"(r[3]) : "r"(a));
}
__device__ __forceinline__ void mma16816(float c[4], const uint32_t a[4],
                                         uint32_t b0, uint32_t b1) {
    asm volatile("mma.sync.aligned.m16n8k16.row.col.f32.f16.f16.f32 "
        "{%0,%1,%2,%3}, {%4,%5,%6,%7}, {%8,%9}, {%0,%1,%2,%3};"
        : "+f"(c[0]), "+f"(c[1]), "+f"(c[2]), "+f"(c[3])
        : "r"(a[0]), "r"(a[1]), "r"(a[2]), "r"(a[3]), "r"(b0), "r"(b1));
}
__device__ __forceinline__ void mma16816h(uint32_t c[2], const uint32_t a[4],
                                          uint32_t b0, uint32_t b1) {
    asm volatile("mma.sync.aligned.m16n8k16.row.col.f16.f16.f16.f16 "
        "{%0,%1}, {%2,%3,%4,%5}, {%6,%7}, {%0,%1};"
        : "+r"(c[0]), "+r"(c[1])
        : "r"(a[0]), "r"(a[1]), "r"(a[2]), "r"(a[3]), "r"(b0), "r"(b1));
}
__device__ __forceinline__ uint32_t packh2(float lo, float hi) {
    __half2 h = __floats2half2_rn(lo, hi);
    return *reinterpret_cast<uint32_t*>(&h);
}
__device__ __forceinline__ void cp16(void* s, const void* g) {
    asm volatile("cp.async.cg.shared.global [%0], [%1], 16;"
        :: "r"(smem_u32(s)), "l"(g));
}
__device__ __forceinline__ void cp_commit() {
    asm volatile("cp.async.commit_group;");
}
template <int N> __device__ __forceinline__ void cp_wait() {
    asm volatile("cp.async.wait_group %0;" :: "n"(N));
}
__device__ __forceinline__ uint32_t h2ex2(uint32_t x) {
    uint32_t r;
    asm("ex2.approx.f16x2 %0, %1;" : "=r"(r) : "r"(x));
    return r;
}
__device__ __forceinline__ __half2 u2h2(uint32_t x) {
    return *reinterpret_cast<__half2*>(&x);
}

// ---------------------------------------------------------------------------
__global__ void f2h_all(const float* __restrict__ x, const float* __restrict__ wq,
                        const float* __restrict__ wo,
                        __half* __restrict__ xh, __half* __restrict__ wqh,
                        __half* __restrict__ woh)
{
    int i = (blockIdx.x * blockDim.x + threadIdx.x) * 4;
    const float* s; __half* d; float sc = 1.0f; int j;
    if (i < NX)            { s = x;  d = xh;  j = i; }
    else if (i < NX + NQ)  { j = i - NX; s = wq; d = wqh;
                             if (j < HID * DIM) sc = QPRESCALE; }
    else if (i < NX+NQ+NO) { j = i - NX - NQ; s = wo; d = woh; }
    else return;
    float4 v = *(const float4*)(s + j);
    *(uint32_t*)(d + j)     = packh2(v.x * sc, v.y * sc);
    *(uint32_t*)(d + j + 2) = packh2(v.z * sc, v.w * sc);
}

// ---------------------------------------------------------------------------
// fp16 tensor-core GEMM, generalized (BM, BN) — R14-proven, unchanged.
// ---------------------------------------------------------------------------
template <int BM, int BN, bool OUT_HALF, bool HAS_BIAS>
__global__ __launch_bounds__((BM / 32) * 64)
void hgemm_kernel(const __half* __restrict__ A, const __half* __restrict__ Bg,
                  void* __restrict__ Cg, const float* __restrict__ bias,
                  int M, int N, int K)
{
    constexpr int THREADS = (BM / 32) * 64;
    constexpr int NSPAN = BN / 2;
    constexpr int NT = NSPAN / 8;
    constexpr int BPITCH = BN + 8;
    constexpr int A_SZ = BM * 72;
    constexpr int B_SZ = 64 * BPITCH;

    const int b = blockIdx.z;
    const __half* Bm = Bg + (size_t)b * K * N;
    const int rowC0 = blockIdx.y * BM;
    const int colC0 = blockIdx.x * BN;

    extern __shared__ __half dsm[];
    __half* As = dsm;
    __half* Bs = dsm + 3 * A_SZ;

    const int tid = threadIdx.x, lane = tid & 31, warp = tid >> 5;
    const int g = lane >> 2, tg = lane & 3;
    const int wm = warp >> 1, wn = warp & 1;

    const int lm_koff = ((lane >> 3) & 1) * 8 + (lane & 7);
    const int lm_noff = wn * NSPAN + ((lane >> 4) & 1) * 8;

    auto stage = [&](int buf, int k0) {
        __half* Ab = As + buf * A_SZ;
        #pragma unroll
        for (int it = 0; it < BM * 8 / THREADS; it++) {
            int c = tid + it * THREADS;
            int m = c >> 3, o8 = (c & 7) * 8;
            cp16(Ab + m * 72 + o8, A + (size_t)(rowC0 + m) * K + k0 + o8);
        }
        __half* Bb = Bs + buf * B_SZ;
        #pragma unroll
        for (int it = 0; it < BN * 8 / THREADS; it++) {
            int c = tid + it * THREADS;
            int kk = c / (BN / 8), n8 = (c % (BN / 8)) * 8;
            cp16(Bb + kk * BPITCH + n8, Bm + (size_t)(k0 + kk) * N + colC0 + n8);
        }
    };

    float acc[2][NT][4] = {};
    const int ntiles = K >> 6;

    stage(0, 0);
    cp_commit();
    if (ntiles > 1) stage(1, 64);
    cp_commit();

    for (int kt = 0; kt < ntiles; kt++) {
        const int cur = kt % 3;
        cp_wait<1>();
        __syncthreads();

        const __half* Ab = As + cur * A_SZ;
        const uint32_t bsb = smem_u32(Bs + cur * B_SZ);
        #pragma unroll
        for (int kc = 0; kc < 4; kc++) {
            uint32_t af[2][4];
            #pragma unroll
            for (int mt = 0; mt < 2; mt++) {
                const __half* ap = Ab + (wm * 32 + mt * 16) * 72 + 16 * kc + 2 * tg;
                af[mt][0] = *(const uint32_t*)(ap + g * 72);
                af[mt][1] = *(const uint32_t*)(ap + (g + 8) * 72);
                af[mt][2] = *(const uint32_t*)(ap + g * 72 + 8);
                af[mt][3] = *(const uint32_t*)(ap + (g + 8) * 72 + 8);
            }
            uint32_t bf[NT][2];
            #pragma unroll
            for (int ntp = 0; ntp < NT / 2; ntp++) {
                uint32_t r[4];
                uint32_t a = bsb + 2 * ((16 * kc + lm_koff) * BPITCH +
                                        lm_noff + 16 * ntp);
                ldsm_x4t(r, a);
                bf[2*ntp][0] = r[0]; bf[2*ntp][1] = r[1];
                bf[2*ntp+1][0] = r[2]; bf[2*ntp+1][1] = r[3];
            }
            #pragma unroll
            for (int nt = 0; nt < NT; nt++)
                #pragma unroll
                for (int mt = 0; mt < 2; mt++)
                    mma16816(acc[mt][nt], af[mt], bf[nt][0], bf[nt][1]);
        }

        if (kt + 2 < ntiles) stage((kt + 2) % 3, (kt + 2) * 64);
        cp_commit();
    }

    #pragma unroll
    for (int mt = 0; mt < 2; mt++) {
        int m0 = rowC0 + wm * 32 + mt * 16 + g;
        #pragma unroll
        for (int nt = 0; nt < NT; nt++) {
            int n = colC0 + wn * NSPAN + nt * 8 + 2 * tg;
            float c0 = acc[mt][nt][0], c1 = acc[mt][nt][1];
            float c2 = acc[mt][nt][2], c3 = acc[mt][nt][3];
            if (OUT_HALF) {
                __half* Ch = (__half*)Cg + (size_t)b * M * N;
                *(uint32_t*)(Ch + (size_t)m0 * N + n)       = packh2(c0, c1);
                *(uint32_t*)(Ch + (size_t)(m0 + 8) * N + n) = packh2(c2, c3);
            } else {
                float* Cf = (float*)Cg + (size_t)b * M * N;
                float bv0 = HAS_BIAS ? bias[m0] : 0.0f;
                float bv1 = HAS_BIAS ? bias[m0 + 8] : 0.0f;
                *(float2*)(Cf + (size_t)m0 * N + n)       = make_float2(c0 + bv0, c1 + bv0);
                *(float2*)(Cf + (size_t)(m0 + 8) * N + n) = make_float2(c2 + bv1, c3 + bv1);
            }
        }
    }
}

// ---------------------------------------------------------------------------
// Split-KV fp16 flash attention. Each CTA = (q-tile, head, batch, split) does
// STILES=8 KV tiles starting at split*512 and writes UNNORMALIZED fp32 O
// partials + fp32 l partials. Mainloop is the R12/R14-proven pipelined body.
// ---------------------------------------------------------------------------
#define KVB 9216
#define KS_OFF 18432
#define V01_OFF (18432 + 3 * KVB)
#define FL_BYTES (V01_OFF + 2 * KVB)  // 64512

__global__ __launch_bounds__(128)
void flash_kernel(const __half* __restrict__ qkv,
                  float* __restrict__ op, float* __restrict__ lp)
{
    const int b = blockIdx.z & (BATCH - 1);
    const int sp = blockIdx.z >> 2;
    const int h = blockIdx.y;
    const int i0 = blockIdx.x * 128;
    const int sbase = sp * (LL / NSPLIT);
    const int tid = threadIdx.x, lane = tid & 31, warp = tid >> 5;
    const int g = lane >> 2, tg = lane & 3;

    const __half* qg = qkv + ((size_t)b * QKV_ROWS + h * DHEAD) * LL;
    const __half* kg = qkv + ((size_t)b * QKV_ROWS + HID + h * DHEAD) * LL;
    const __half* vg = qkv + ((size_t)b * QKV_ROWS + 2 * HID + h * DHEAD) * LL;

    extern __shared__ __half sm[];
    __half* QV = sm;                          // Q staging / V2,V3 / O transpose
    const uint32_t sb = smem_u32(sm);

    auto stageK = [&](int buf, int j0) {
        __half* Kb = (__half*)((char*)sm + KS_OFF + buf * KVB);
        #pragma unroll
        for (int it = 0; it < 4; it++) {
            int idx = tid + it * 128;
            int d = idx >> 3, c8 = (idx & 7) * 8;
            cp16(Kb + d * 72 + c8, kg + (size_t)d * LL + j0 + c8);
        }
    };
    auto stageV = [&](int buf, int j0) {
        __half* Vb = (__half*)((char*)sm +
                     ((buf & 2) ? (buf & 1) * KVB : V01_OFF + (buf & 1) * KVB));
        #pragma unroll
        for (int it = 0; it < 4; it++) {
            int idx = tid + it * 128;
            int d = idx >> 3, c8 = (idx & 7) * 8;
            cp16(Vb + d * 72 + c8, vg + (size_t)d * LL + j0 + c8);
        }
    };

    // Prologue
    stageK(0, sbase);        stageV(0, sbase);        cp_commit();
    stageK(1, sbase + 64);   stageV(1, sbase + 64);   cp_commit();

    #pragma unroll
    for (int it = 0; it < 8; it++) {
        int idx = tid + it * 128;
        int d = idx >> 4, q8 = (idx & 15) * 8;
        *(uint4*)(QV + d * 136 + q8) = *(const uint4*)(qg + (size_t)d * LL + i0 + q8);
    }
    __syncthreads();

    uint32_t qa[2][4][4];
    {
        int row = lane & 7;
        int c_off = ((lane >> 3) & 1) * 8;
        int d_off = ((lane >> 4) & 1) * 8;
        #pragma unroll
        for (int mt = 0; mt < 2; mt++)
            #pragma unroll
            for (int kc = 0; kc < 4; kc++) {
                uint32_t a = sb + 2 * ((16 * kc + d_off + row) * 136 +
                                       warp * 32 + mt * 16 + c_off);
                ldsm_x4t(qa[mt][kc], a);
            }
    }

    cp_wait<1>();
    __syncthreads();

    const int lmr = lane & 7;
    const int lmo1 = ((lane >> 3) & 1) * 8;
    const int lmo2 = ((lane >> 4) & 1) * 8;

    float oc[2][8][4] = {};
    float lr[2][2] = {};
    uint32_t schA[2][8][2], schB[2][8][2];

    // S(0)
    {
        #pragma unroll
        for (int mt = 0; mt < 2; mt++)
            #pragma unroll
            for (int jc = 0; jc < 8; jc++) { schA[mt][jc][0] = 0; schA[mt][jc][1] = 0; }
        const uint32_t kbb = sb + KS_OFF;
        #pragma unroll
        for (int kc = 0; kc < 4; kc++) {
            uint32_t kb[8][2];
            #pragma unroll
            for (int jp = 0; jp < 4; jp++) {
                uint32_t r[4];
                uint32_t a = kbb + 2 * ((16 * kc + lmo1 + lmr) * 72 + 16 * jp + lmo2);
                ldsm_x4t(r, a);
                kb[2*jp][0] = r[0]; kb[2*jp][1] = r[1];
                kb[2*jp+1][0] = r[2]; kb[2*jp+1][1] = r[3];
            }
            #pragma unroll
            for (int jc = 0; jc < 8; jc++)
                #pragma unroll
                for (int mt = 0; mt < 2; mt++)
                    mma16816h(schA[mt][jc], qa[mt][kc], kb[jc][0], kb[jc][1]);
        }
    }

    auto body = [&](uint32_t (&si)[2][8][2], uint32_t (&so)[2][8][2], int t) {
        if (t + 2 < STILES) { stageK((t + 2) % 3, sbase + (t + 2) * 64);
                              stageV((t + 2) & 3, sbase + (t + 2) * 64); }
        cp_commit();
        cp_wait<1>();
        __syncthreads();

        const bool doS = (t + 1 < STILES);
        const uint32_t kbb = sb + KS_OFF + ((t + 1) % 3) * KVB;
        const uint32_t vbb = sb + ((t & 2) ? (t & 1) * KVB
                                           : V01_OFF + (t & 1) * KVB);
        if (doS) {
            #pragma unroll
            for (int mt = 0; mt < 2; mt++)
                #pragma unroll
                for (int jc = 0; jc < 8; jc++) { so[mt][jc][0] = 0; so[mt][jc][1] = 0; }
        }

        __half2 hl[2][2] = {{__half2(0,0), __half2(0,0)},
                            {__half2(0,0), __half2(0,0)}};
        #pragma unroll
        for (int blk = 0; blk < 4; blk++) {
            if (doS) {
                uint32_t kb[8][2];
                #pragma unroll
                for (int jp = 0; jp < 4; jp++) {
                    uint32_t r[4];
                    uint32_t a = kbb + 2 * ((16 * blk + lmo1 + lmr) * 72 +
                                            16 * jp + lmo2);
                    ldsm_x4t(r, a);
                    kb[2*jp][0] = r[0]; kb[2*jp][1] = r[1];
                    kb[2*jp+1][0] = r[2]; kb[2*jp+1][1] = r[3];
                }
                #pragma unroll
                for (int jc = 0; jc < 8; jc++)
                    #pragma unroll
                    for (int mt = 0; mt < 2; mt++)
                        mma16816h(so[mt][jc], qa[mt][blk], kb[jc][0], kb[jc][1]);
            }
            uint32_t pa[2][4];
            #pragma unroll
            for (int mt = 0; mt < 2; mt++) {
                pa[mt][0] = h2ex2(si[mt][2*blk][0]);
                pa[mt][1] = h2ex2(si[mt][2*blk][1]);
                pa[mt][2] = h2ex2(si[mt][2*blk+1][0]);
                pa[mt][3] = h2ex2(si[mt][2*blk+1][1]);
                hl[mt][0] = __hadd2(hl[mt][0], __hadd2(u2h2(pa[mt][0]), u2h2(pa[mt][2])));
                hl[mt][1] = __hadd2(hl[mt][1], __hadd2(u2h2(pa[mt][1]), u2h2(pa[mt][3])));
            }
            #pragma unroll
            for (int dp = 0; dp < 4; dp++) {
                uint32_t r[4];
                uint32_t a = vbb + 2 * ((16 * dp + lmo2 + lmr) * 72 +
                                        16 * blk + lmo1);
                ldsm_x4(r, a);
                #pragma unroll
                for (int mt = 0; mt < 2; mt++) {
                    mma16816(oc[mt][2*dp],   pa[mt], r[0], r[1]);
                    mma16816(oc[mt][2*dp+1], pa[mt], r[2], r[3]);
                }
            }
        }
        #pragma unroll
        for (int mt = 0; mt < 2; mt++) {
            float2 f0 = __half22float2(hl[mt][0]);
            float2 f1 = __half22float2(hl[mt][1]);
            lr[mt][0] += f0.x + f0.y;
            lr[mt][1] += f1.x + f1.y;
        }
    };

    for (int jt = 0; jt < STILES; jt += 2) {
        body(schA, schB, jt);
        body(schB, schA, jt + 1);
    }

    // Quad-reduce l partials; write (lanes tg==0 cover 8 rows each)
    float* lrow = lp + ((size_t)(sp * BATCH + b) * HEADS + h) * LL + i0;
    #pragma unroll
    for (int mt = 0; mt < 2; mt++)
        #pragma unroll
        for (int rr = 0; rr < 2; rr++) {
            lr[mt][rr] += __shfl_xor_sync(~0u, lr[mt][rr], 1);
            lr[mt][rr] += __shfl_xor_sync(~0u, lr[mt][rr], 2);
            if (tg == 0) lrow[warp * 32 + mt * 16 + rr * 8 + g] = lr[mt][rr];
        }

    // O partials (fp32, unnormalized): two-pass transpose through QV (as f32)
    float* QVf = (float*)sm;                  // 32 x 136 f32 = 17408 B fits
    float* og = op + ((size_t)(sp * BATCH + b) * HID + h * DHEAD) * LL;
    #pragma unroll
    for (int p = 0; p < 2; p++) {
        __syncthreads();                      // prior reads of QV / QVf done
        #pragma unroll
        for (int mt = 0; mt < 2; mt++) {
            int r_lo = warp * 32 + mt * 16 + g, r_hi = r_lo + 8;
            #pragma unroll
            for (int dc = p * 4; dc < p * 4 + 4; dc++) {
                int dl = dc * 8 + 2 * tg - p * 32;
                QVf[dl * 136 + r_lo]       = oc[mt][dc][0];
                QVf[(dl + 1) * 136 + r_lo] = oc[mt][dc][1];
                QVf[dl * 136 + r_hi]       = oc[mt][dc][2];
                QVf[(dl + 1) * 136 + r_hi] = oc[mt][dc][3];
            }
        }
        __syncthreads();
        #pragma unroll
        for (int it = 0; it < 8; it++) {
            int task = tid + it * 128;        // 1024 float4
            int d = task >> 5, i4 = (task & 31) * 4;
            *(float4*)(og + (size_t)(p * 32 + d) * LL + i0 + i4) =
                *(const float4*)(QVf + d * 136 + i4);
        }
    }
}

// ---------------------------------------------------------------------------
// Combine: ao[b,hd,i] = (sum_s O_s) / (sum_s l_s), fp16 out.
// CTA = (b, h, 512-wide i chunk), 256 threads.
// ---------------------------------------------------------------------------
__global__ __launch_bounds__(256)
void combine_kernel(const float* __restrict__ op, const float* __restrict__ lp,
                    __half* __restrict__ ao)
{
    const int b = blockIdx.z, h = blockIdx.y;
    const int i0 = blockIdx.x * 512;
    const int tid = threadIdx.x;
    __shared__ float inv[512];

    #pragma unroll
    for (int it = 0; it < 2; it++) {
        int i = tid + it * 256;
        float s = 0.0f;
        #pragma unroll
        for (int sp = 0; sp < NSPLIT; sp++)
            s += lp[((size_t)(sp * BATCH + b) * HEADS + h) * LL + i0 + i];
        inv[i] = 1.0f / s;
    }
    __syncthreads();

    #pragma unroll
    for (int it = 0; it < 32; it++) {
        int task = tid + it * 256;            // 8192: 64 d x 128 i-vec4
        int d = task >> 7, iv = (task & 127) * 4;
        float4 acc = make_float4(0.f, 0.f, 0.f, 0.f);
        #pragma unroll
        for (int sp = 0; sp < NSPLIT; sp++) {
            const float* p = op + ((size_t)(sp * BATCH + b) * HID +
                                   h * DHEAD + d) * LL + i0 + iv;
            float4 v = *(const float4*)p;
            acc.x += v.x; acc.y += v.y; acc.z += v.z; acc.w += v.w;
        }
        uint32_t o01 = packh2(acc.x * inv[iv],     acc.y * inv[iv + 1]);
        uint32_t o23 = packh2(acc.z * inv[iv + 2], acc.w * inv[iv + 3]);
        uint2 o = make_uint2(o01, o23);
        *(uint2*)(ao + ((size_t)b * HID + h * DHEAD + d) * LL + i0 + iv) = o;
    }
}

// ---------------------------------------------------------------------------
extern "C" void kernel_launch(void* const* d_in, const int* in_sizes, int n_in,
                              void* d_out, int out_size)
{
    (void)in_sizes; (void)n_in; (void)out_size;
    const float* x     = (const float*)d_in[0];
    const float* w_qkv = (const float*)d_in[1];
    const float* w_out = (const float*)d_in[2];
    const float* b_out = (const float*)d_in[3];
    float* out = (float*)d_out;

    __half *qkv, *ao, *xh, *wqk, *wo;
    float *op, *lpp;
    cudaGetSymbolAddress((void**)&qkv, g_qkv);
    cudaGetSymbolAddress((void**)&ao,  g_ao);
    cudaGetSymbolAddress((void**)&xh,  g_xh);
    cudaGetSymbolAddress((void**)&wqk, g_wqk);
    cudaGetSymbolAddress((void**)&wo,  g_wo);
    cudaGetSymbolAddress((void**)&op,  g_opf);
    cudaGetSymbolAddress((void**)&lpp, g_lpf);

    {
        int total4 = (NX + NQ + NO) / 4;
        f2h_all<<<(total4 + 255) / 256, 256>>>(x, w_qkv, w_out, xh, wqk, wo);
    }

    const int gm1_smem = 3 * (128 * 72 + 64 * 136) * 2;   // 107520
    const int gm3_smem = 3 * (64 * 72 + 64 * 72) * 2;     // 55296
    cudaFuncSetAttribute((const void*)hgemm_kernel<128, 128, true, false>,
                         cudaFuncAttributeMaxDynamicSharedMemorySize, gm1_smem);
    cudaFuncSetAttribute((const void*)hgemm_kernel<64, 64, false, true>,
                         cudaFuncAttributeMaxDynamicSharedMemorySize, gm3_smem);
    cudaFuncSetAttribute((const void*)flash_kernel,
                         cudaFuncAttributeMaxDynamicSharedMemorySize, FL_BYTES);

    // 1) QKV projection
    dim3 g1(LL / 128, QKV_ROWS / 128, BATCH);
    hgemm_kernel<128, 128, true, false><<<g1, 256, gm1_smem>>>(
        wqk, xh, qkv, nullptr, QKV_ROWS, LL, DIM);

    // 2) Split-KV flash attention (2048 CTAs)
    dim3 g2(LL / 128, HEADS, BATCH * NSPLIT);
    flash_kernel<<<g2, 128, FL_BYTES>>>(qkv, op, lpp);

    // 2b) Combine partials -> ao (fp16)
    dim3 gc(LL / 512, HEADS, BATCH);
    combine_kernel<<<gc, 256>>>(op, lpp, ao);

    // 3) Output projection + bias
    dim3 g3(LL / 64, DIM / 64, BATCH);
    hgemm_kernel<64, 64, false, true><<<g3, 128, gm3_smem>>>(
        wo, ao, out, b_out, DIM, LL, HID);
}

// round 16
// speedup vs baseline: 1.1985x; 1.1985x over previous
#include <cuda_runtime.h>
#include <cuda_fp16.h>
#include <stdint.h>

#define BATCH 4
#define DIM 256
#define LL 2048
#define HEADS 8
#define DHEAD 64
#define HID 512
#define QKV_ROWS 1536
#define QPRESCALE 0.18033688011112042f

#define NX (BATCH * DIM * LL)
#define NQ (QKV_ROWS * DIM)
#define NO (DIM * HID)

__device__ __half g_qkv [(size_t)BATCH * QKV_ROWS * LL];
__device__ __half g_ao  [(size_t)BATCH * HID * LL];
__device__ __half g_xh  [NX];
__device__ __half g_wqk [NQ];
__device__ __half g_wo  [NO];

// ---------------------------------------------------------------------------
// PTX helpers
// ---------------------------------------------------------------------------
__device__ __forceinline__ uint32_t smem_u32(const void* p) {
    return (uint32_t)__cvta_generic_to_shared(p);
}
__device__ __forceinline__ void ldsm_x4(uint32_t r[4], uint32_t a) {
    asm volatile("ldmatrix.sync.aligned.m8n8.x4.shared.b16 {%0,%1,%2,%3}, [%4];"
        : "=r"(r[0]), "=r"(r[1]), "=r"(r[2]), "=r"(r[3]) : "r"(a));
}
__device__ __forceinline__ void ldsm_x4t(uint32_t r[4], uint32_t a) {
    asm volatile("ldmatrix.sync.aligned.m8n8.x4.trans.shared.b16 {%0,%1,%2,%3}, [%4];"
        : "=r"(r[0]), "=r"(r[1]), "=r"(r[2]), "=r"(r[3]) : "r"(a));
}
__device__ __forceinline__ void mma16816(float c[4], const uint32_t a[4],
                                         uint32_t b0, uint32_t b1) {
    asm volatile("mma.sync.aligned.m16n8k16.row.col.f32.f16.f16.f32 "
        "{%0,%1,%2,%3}, {%4,%5,%6,%7}, {%8,%9}, {%0,%1,%2,%3};"
        : "+f"(c[0]), "+f"(c[1]), "+f"(c[2]), "+f"(c[3])
        : "r"(a[0]), "r"(a[1]), "r"(a[2]), "r"(a[3]), "r"(b0), "r"(b1));
}
__device__ __forceinline__ void mma16816h(uint32_t c[2], const uint32_t a[4],
                                          uint32_t b0, uint32_t b1) {
    asm volatile("mma.sync.aligned.m16n8k16.row.col.f16.f16.f16.f16 "
        "{%0,%1}, {%2,%3,%4,%5}, {%6,%7}, {%0,%1};"
        : "+r"(c[0]), "+r"(c[1])
        : "r"(a[0]), "r"(a[1]), "r"(a[2]), "r"(a[3]), "r"(b0), "r"(b1));
}
__device__ __forceinline__ uint32_t packh2(float lo, float hi) {
    __half2 h = __floats2half2_rn(lo, hi);
    return *reinterpret_cast<uint32_t*>(&h);
}
__device__ __forceinline__ void cp16(void* s, const void* g) {
    asm volatile("cp.async.cg.shared.global [%0], [%1], 16;"
        :: "r"(smem_u32(s)), "l"(g));
}
__device__ __forceinline__ void cp_commit() {
    asm volatile("cp.async.commit_group;");
}
template <int N> __device__ __forceinline__ void cp_wait() {
    asm volatile("cp.async.wait_group %0;" :: "n"(N));
}
__device__ __forceinline__ uint32_t h2ex2(uint32_t x) {
    uint32_t r;
    asm("ex2.approx.f16x2 %0, %1;" : "=r"(r) : "r"(x));
    return r;
}
__device__ __forceinline__ __half2 u2h2(uint32_t x) {
    return *reinterpret_cast<__half2*>(&x);
}

// ---------------------------------------------------------------------------
__global__ void f2h_all(const float* __restrict__ x, const float* __restrict__ wq,
                        const float* __restrict__ wo,
                        __half* __restrict__ xh, __half* __restrict__ wqh,
                        __half* __restrict__ woh)
{
    int i = (blockIdx.x * blockDim.x + threadIdx.x) * 4;
    const float* s; __half* d; float sc = 1.0f; int j;
    if (i < NX)            { s = x;  d = xh;  j = i; }
    else if (i < NX + NQ)  { j = i - NX; s = wq; d = wqh;
                             if (j < HID * DIM) sc = QPRESCALE; }
    else if (i < NX+NQ+NO) { j = i - NX - NQ; s = wo; d = woh; }
    else return;
    float4 v = *(const float4*)(s + j);
    *(uint32_t*)(d + j)     = packh2(v.x * sc, v.y * sc);
    *(uint32_t*)(d + j + 2) = packh2(v.z * sc, v.w * sc);
}

// ---------------------------------------------------------------------------
// fp16 tensor-core GEMM, generalized (BM, BN). BK=64. TWO-buffer cp.async
// ring with race-free overlap ordering:
//   wait<0> -> __syncthreads -> stage(kt+1) -> commit -> compute(kt)
// After the barrier, every thread has passed wait<0>, so ALL copies of G(kt)
// (any thread's) are visible; the buffer being staged was last read in
// compute(kt-1), which precedes the same barrier. G(kt+1) overlaps compute.
// ---------------------------------------------------------------------------
template <int BM, int BN, bool OUT_HALF, bool HAS_BIAS>
__global__ __launch_bounds__((BM / 32) * 64)
void hgemm_kernel(const __half* __restrict__ A, const __half* __restrict__ Bg,
                  void* __restrict__ Cg, const float* __restrict__ bias,
                  int M, int N, int K)
{
    constexpr int THREADS = (BM / 32) * 64;
    constexpr int NSPAN = BN / 2;
    constexpr int NT = NSPAN / 8;
    constexpr int BPITCH = BN + 8;
    constexpr int A_SZ = BM * 72;
    constexpr int B_SZ = 64 * BPITCH;

    const int b = blockIdx.z;
    const __half* Bm = Bg + (size_t)b * K * N;
    const int rowC0 = blockIdx.y * BM;
    const int colC0 = blockIdx.x * BN;

    extern __shared__ __half dsm[];
    __half* As = dsm;                 // [2][BM][72]
    __half* Bs = dsm + 2 * A_SZ;      // [2][64][BPITCH]

    const int tid = threadIdx.x, lane = tid & 31, warp = tid >> 5;
    const int g = lane >> 2, tg = lane & 3;
    const int wm = warp >> 1, wn = warp & 1;

    const int lm_koff = ((lane >> 3) & 1) * 8 + (lane & 7);
    const int lm_noff = wn * NSPAN + ((lane >> 4) & 1) * 8;

    auto stage = [&](int buf, int k0) {
        __half* Ab = As + buf * A_SZ;
        #pragma unroll
        for (int it = 0; it < BM * 8 / THREADS; it++) {
            int c = tid + it * THREADS;
            int m = c >> 3, o8 = (c & 7) * 8;
            cp16(Ab + m * 72 + o8, A + (size_t)(rowC0 + m) * K + k0 + o8);
        }
        __half* Bb = Bs + buf * B_SZ;
        #pragma unroll
        for (int it = 0; it < BN * 8 / THREADS; it++) {
            int c = tid + it * THREADS;
            int kk = c / (BN / 8), n8 = (c % (BN / 8)) * 8;
            cp16(Bb + kk * BPITCH + n8, Bm + (size_t)(k0 + kk) * N + colC0 + n8);
        }
    };

    float acc[2][NT][4] = {};
    const int ntiles = K >> 6;

    stage(0, 0);
    cp_commit();

    for (int kt = 0; kt < ntiles; kt++) {
        const int cur = kt & 1;
        cp_wait<0>();          // own copies of ALL committed groups done
        __syncthreads();       // => everyone's G(kt) done; buf cur^1 free

        if (kt + 1 < ntiles) stage(cur ^ 1, (kt + 1) * 64);
        cp_commit();           // G(kt+1) overlaps compute below

        const __half* Ab = As + cur * A_SZ;
        const uint32_t bsb = smem_u32(Bs + cur * B_SZ);
        #pragma unroll
        for (int kc = 0; kc < 4; kc++) {
            uint32_t af[2][4];
            #pragma unroll
            for (int mt = 0; mt < 2; mt++) {
                const __half* ap = Ab + (wm * 32 + mt * 16) * 72 + 16 * kc + 2 * tg;
                af[mt][0] = *(const uint32_t*)(ap + g * 72);
                af[mt][1] = *(const uint32_t*)(ap + (g + 8) * 72);
                af[mt][2] = *(const uint32_t*)(ap + g * 72 + 8);
                af[mt][3] = *(const uint32_t*)(ap + (g + 8) * 72 + 8);
            }
            uint32_t bf[NT][2];
            #pragma unroll
            for (int ntp = 0; ntp < NT / 2; ntp++) {
                uint32_t r[4];
                uint32_t a = bsb + 2 * ((16 * kc + lm_koff) * BPITCH +
                                        lm_noff + 16 * ntp);
                ldsm_x4t(r, a);
                bf[2*ntp][0] = r[0]; bf[2*ntp][1] = r[1];
                bf[2*ntp+1][0] = r[2]; bf[2*ntp+1][1] = r[3];
            }
            #pragma unroll
            for (int nt = 0; nt < NT; nt++)
                #pragma unroll
                for (int mt = 0; mt < 2; mt++)
                    mma16816(acc[mt][nt], af[mt], bf[nt][0], bf[nt][1]);
        }
    }

    #pragma unroll
    for (int mt = 0; mt < 2; mt++) {
        int m0 = rowC0 + wm * 32 + mt * 16 + g;
        #pragma unroll
        for (int nt = 0; nt < NT; nt++) {
            int n = colC0 + wn * NSPAN + nt * 8 + 2 * tg;
            float c0 = acc[mt][nt][0], c1 = acc[mt][nt][1];
            float c2 = acc[mt][nt][2], c3 = acc[mt][nt][3];
            if (OUT_HALF) {
                __half* Ch = (__half*)Cg + (size_t)b * M * N;
                *(uint32_t*)(Ch + (size_t)m0 * N + n)       = packh2(c0, c1);
                *(uint32_t*)(Ch + (size_t)(m0 + 8) * N + n) = packh2(c2, c3);
            } else {
                float* Cf = (float*)Cg + (size_t)b * M * N;
                float bv0 = HAS_BIAS ? bias[m0] : 0.0f;
                float bv1 = HAS_BIAS ? bias[m0 + 8] : 0.0f;
                *(float2*)(Cf + (size_t)m0 * N + n)       = make_float2(c0 + bv0, c1 + bv0);
                *(float2*)(Cf + (size_t)(m0 + 8) * N + n) = make_float2(c2 + bv1, c3 + bv1);
            }
        }
    }
}

// ---------------------------------------------------------------------------
// fp16 flash attention — exact R12/R14 version (proven at 139.7us / 6.95e-4).
// 4 warps x 32 q-rows, pipelined across KV tiles (S(t+1) with exp/PV(t)).
// K triple-buffered, V quad-buffered (V2,V3 alias dead Q staging).
// ---------------------------------------------------------------------------
#define NTILES 32
#define KVB 9216
#define KS_OFF 18432
#define V01_OFF (18432 + 3 * KVB)
#define FL_BYTES (V01_OFF + 2 * KVB)  // 64512

__global__ __launch_bounds__(128)
void flash_kernel(const __half* __restrict__ qkv, __half* __restrict__ ao)
{
    const int b = blockIdx.z, h = blockIdx.y;
    const int i0 = blockIdx.x * 128;
    const int tid = threadIdx.x, lane = tid & 31, warp = tid >> 5;
    const int g = lane >> 2, tg = lane & 3;

    const __half* qg = qkv + ((size_t)b * QKV_ROWS + h * DHEAD) * LL;
    const __half* kg = qkv + ((size_t)b * QKV_ROWS + HID + h * DHEAD) * LL;
    const __half* vg = qkv + ((size_t)b * QKV_ROWS + 2 * HID + h * DHEAD) * LL;

    extern __shared__ __half sm[];
    __half* QV = sm;
    const uint32_t sb = smem_u32(sm);

    auto stageK = [&](int buf, int j0) {
        __half* Kb = (__half*)((char*)sm + KS_OFF + buf * KVB);
        #pragma unroll
        for (int it = 0; it < 4; it++) {
            int idx = tid + it * 128;
            int d = idx >> 3, c8 = (idx & 7) * 8;
            cp16(Kb + d * 72 + c8, kg + (size_t)d * LL + j0 + c8);
        }
    };
    auto stageV = [&](int buf, int j0) {
        __half* Vb = (__half*)((char*)sm +
                     ((buf & 2) ? (buf & 1) * KVB : V01_OFF + (buf & 1) * KVB));
        #pragma unroll
        for (int it = 0; it < 4; it++) {
            int idx = tid + it * 128;
            int d = idx >> 3, c8 = (idx & 7) * 8;
            cp16(Vb + d * 72 + c8, vg + (size_t)d * LL + j0 + c8);
        }
    };

    stageK(0, 0);    stageV(0, 0);    cp_commit();
    stageK(1, 64);   stageV(1, 64);   cp_commit();

    #pragma unroll
    for (int it = 0; it < 8; it++) {
        int idx = tid + it * 128;
        int d = idx >> 4, q8 = (idx & 15) * 8;
        *(uint4*)(QV + d * 136 + q8) = *(const uint4*)(qg + (size_t)d * LL + i0 + q8);
    }
    __syncthreads();

    uint32_t qa[2][4][4];
    {
        int row = lane & 7;
        int c_off = ((lane >> 3) & 1) * 8;
        int d_off = ((lane >> 4) & 1) * 8;
        #pragma unroll
        for (int mt = 0; mt < 2; mt++)
            #pragma unroll
            for (int kc = 0; kc < 4; kc++) {
                uint32_t a = sb + 2 * ((16 * kc + d_off + row) * 136 +
                                       warp * 32 + mt * 16 + c_off);
                ldsm_x4t(qa[mt][kc], a);
            }
    }

    cp_wait<1>();
    __syncthreads();

    const int lmr = lane & 7;
    const int lmo1 = ((lane >> 3) & 1) * 8;
    const int lmo2 = ((lane >> 4) & 1) * 8;

    float oc[2][8][4] = {};
    float lr[2][2] = {};
    uint32_t schA[2][8][2], schB[2][8][2];

    {
        #pragma unroll
        for (int mt = 0; mt < 2; mt++)
            #pragma unroll
            for (int jc = 0; jc < 8; jc++) { schA[mt][jc][0] = 0; schA[mt][jc][1] = 0; }
        const uint32_t kbb = sb + KS_OFF;
        #pragma unroll
        for (int kc = 0; kc < 4; kc++) {
            uint32_t kb[8][2];
            #pragma unroll
            for (int jp = 0; jp < 4; jp++) {
                uint32_t r[4];
                uint32_t a = kbb + 2 * ((16 * kc + lmo1 + lmr) * 72 + 16 * jp + lmo2);
                ldsm_x4t(r, a);
                kb[2*jp][0] = r[0]; kb[2*jp][1] = r[1];
                kb[2*jp+1][0] = r[2]; kb[2*jp+1][1] = r[3];
            }
            #pragma unroll
            for (int jc = 0; jc < 8; jc++)
                #pragma unroll
                for (int mt = 0; mt < 2; mt++)
                    mma16816h(schA[mt][jc], qa[mt][kc], kb[jc][0], kb[jc][1]);
        }
    }

    auto body = [&](uint32_t (&si)[2][8][2], uint32_t (&so)[2][8][2], int t) {
        if (t + 2 < NTILES) { stageK((t + 2) % 3, (t + 2) * 64);
                              stageV((t + 2) & 3, (t + 2) * 64); }
        cp_commit();
        cp_wait<1>();
        __syncthreads();

        const bool doS = (t + 1 < NTILES);
        const uint32_t kbb = sb + KS_OFF + ((t + 1) % 3) * KVB;
        const uint32_t vbb = sb + ((t & 2) ? (t & 1) * KVB
                                           : V01_OFF + (t & 1) * KVB);
        if (doS) {
            #pragma unroll
            for (int mt = 0; mt < 2; mt++)
                #pragma unroll
                for (int jc = 0; jc < 8; jc++) { so[mt][jc][0] = 0; so[mt][jc][1] = 0; }
        }

        __half2 hl[2][2] = {{__half2(0,0), __half2(0,0)},
                            {__half2(0,0), __half2(0,0)}};
        #pragma unroll
        for (int blk = 0; blk < 4; blk++) {
            if (doS) {
                uint32_t kb[8][2];
                #pragma unroll
                for (int jp = 0; jp < 4; jp++) {
                    uint32_t r[4];
                    uint32_t a = kbb + 2 * ((16 * blk + lmo1 + lmr) * 72 +
                                            16 * jp + lmo2);
                    ldsm_x4t(r, a);
                    kb[2*jp][0] = r[0]; kb[2*jp][1] = r[1];
                    kb[2*jp+1][0] = r[2]; kb[2*jp+1][1] = r[3];
                }
                #pragma unroll
                for (int jc = 0; jc < 8; jc++)
                    #pragma unroll
                    for (int mt = 0; mt < 2; mt++)
                        mma16816h(so[mt][jc], qa[mt][blk], kb[jc][0], kb[jc][1]);
            }
            uint32_t pa[2][4];
            #pragma unroll
            for (int mt = 0; mt < 2; mt++) {
                pa[mt][0] = h2ex2(si[mt][2*blk][0]);
                pa[mt][1] = h2ex2(si[mt][2*blk][1]);
                pa[mt][2] = h2ex2(si[mt][2*blk+1][0]);
                pa[mt][3] = h2ex2(si[mt][2*blk+1][1]);
                hl[mt][0] = __hadd2(hl[mt][0], __hadd2(u2h2(pa[mt][0]), u2h2(pa[mt][2])));
                hl[mt][1] = __hadd2(hl[mt][1], __hadd2(u2h2(pa[mt][1]), u2h2(pa[mt][3])));
            }
            #pragma unroll
            for (int dp = 0; dp < 4; dp++) {
                uint32_t r[4];
                uint32_t a = vbb + 2 * ((16 * dp + lmo2 + lmr) * 72 +
                                        16 * blk + lmo1);
                ldsm_x4(r, a);
                #pragma unroll
                for (int mt = 0; mt < 2; mt++) {
                    mma16816(oc[mt][2*dp],   pa[mt], r[0], r[1]);
                    mma16816(oc[mt][2*dp+1], pa[mt], r[2], r[3]);
                }
            }
        }
        #pragma unroll
        for (int mt = 0; mt < 2; mt++) {
            float2 f0 = __half22float2(hl[mt][0]);
            float2 f1 = __half22float2(hl[mt][1]);
            lr[mt][0] += f0.x + f0.y;
            lr[mt][1] += f1.x + f1.y;
        }
    };

    for (int jt = 0; jt < NTILES; jt += 2) {
        body(schA, schB, jt);
        body(schB, schA, jt + 1);
    }

    #pragma unroll
    for (int mt = 0; mt < 2; mt++)
        #pragma unroll
        for (int rr = 0; rr < 2; rr++) {
            lr[mt][rr] += __shfl_xor_sync(~0u, lr[mt][rr], 1);
            lr[mt][rr] += __shfl_xor_sync(~0u, lr[mt][rr], 2);
        }

    __syncthreads();

    #pragma unroll
    for (int mt = 0; mt < 2; mt++) {
        float inv0 = 1.0f / lr[mt][0];
        float inv1 = 1.0f / lr[mt][1];
        int r_lo = warp * 32 + mt * 16 + g, r_hi = r_lo + 8;
        #pragma unroll
        for (int dc = 0; dc < 8; dc++) {
            int d = dc * 8 + 2 * tg;
            QV[d * 136 + r_lo]       = __float2half(oc[mt][dc][0] * inv0);
            QV[(d + 1) * 136 + r_lo] = __float2half(oc[mt][dc][1] * inv0);
            QV[d * 136 + r_hi]       = __float2half(oc[mt][dc][2] * inv1);
            QV[(d + 1) * 136 + r_hi] = __float2half(oc[mt][dc][3] * inv1);
        }
    }
    __syncthreads();

    __half* aog = ao + ((size_t)b * HID + h * DHEAD) * LL;
    #pragma unroll
    for (int it = 0; it < 8; it++) {
        int idx = tid + it * 128;
        int d = idx >> 4, q8 = (idx & 15) * 8;
        *(uint4*)(aog + (size_t)d * LL + i0 + q8) = *(const uint4*)(QV + d * 136 + q8);
    }
}

// ---------------------------------------------------------------------------
extern "C" void kernel_launch(void* const* d_in, const int* in_sizes, int n_in,
                              void* d_out, int out_size)
{
    (void)in_sizes; (void)n_in; (void)out_size;
    const float* x     = (const float*)d_in[0];
    const float* w_qkv = (const float*)d_in[1];
    const float* w_out = (const float*)d_in[2];
    const float* b_out = (const float*)d_in[3];
    float* out = (float*)d_out;

    __half *qkv, *ao, *xh, *wqk, *wo;
    cudaGetSymbolAddress((void**)&qkv, g_qkv);
    cudaGetSymbolAddress((void**)&ao,  g_ao);
    cudaGetSymbolAddress((void**)&xh,  g_xh);
    cudaGetSymbolAddress((void**)&wqk, g_wqk);
    cudaGetSymbolAddress((void**)&wo,  g_wo);

    {
        int total4 = (NX + NQ + NO) / 4;
        f2h_all<<<(total4 + 255) / 256, 256>>>(x, w_qkv, w_out, xh, wqk, wo);
    }

    const int gm1_smem = 2 * (128 * 72 + 64 * 136) * 2;   // 71680 -> 3 CTAs/SM
    const int gm3_smem = 2 * (64 * 72 + 64 * 72) * 2;     // 36864 -> 6 CTAs/SM
    cudaFuncSetAttribute((const void*)hgemm_kernel<128, 128, true, false>,
                         cudaFuncAttributeMaxDynamicSharedMemorySize, gm1_smem);
    cudaFuncSetAttribute((const void*)hgemm_kernel<64, 64, false, true>,
                         cudaFuncAttributeMaxDynamicSharedMemorySize, gm3_smem);
    cudaFuncSetAttribute((const void*)flash_kernel,
                         cudaFuncAttributeMaxDynamicSharedMemorySize, FL_BYTES);

    // 1) QKV projection
    dim3 g1(LL / 128, QKV_ROWS / 128, BATCH);
    hgemm_kernel<128, 128, true, false><<<g1, 256, gm1_smem>>>(
        wqk, xh, qkv, nullptr, QKV_ROWS, LL, DIM);

    // 2) Flash attention (exact R12/R14)
    dim3 g2(LL / 128, HEADS, BATCH);
    flash_kernel<<<g2, 128, FL_BYTES>>>(qkv, ao);

    // 3) Output projection + bias
    dim3 g3(LL / 64, DIM / 64, BATCH);
    hgemm_kernel<64, 64, false, true><<<g3, 128, gm3_smem>>>(
        wo, ao, out, b_out, DIM, LL, HID);
}